// round 1
// baseline (speedup 1.0000x reference)
#include <cuda_runtime.h>

#define NWORD  20000
#define NTOPIC 50
#define NDOC   2000
#define NTOT   22050
#define INDIM  256
#define OUTDIM 128
#define NHEAD  8
#define DKDIM  16
#define NEDGE  150000

// ---------------- scratch (device globals; no runtime allocation) ----------------
__device__ __align__(16) float g_k[NTOT * OUTDIM];
__device__ __align__(16) float g_q[NTOT * OUTDIM];
__device__ __align__(16) float g_v[NTOT * OUTDIM];
__device__ __align__(16) float g_acc[NTOT * OUTDIM];     // t_acc (global node rows)
__device__ __align__(16) float g_u[NWORD * OUTDIM];      // per-etype sum(a*v), local dst idx
__device__ __align__(16) float g_att[NEDGE * NHEAD];     // att, then ex (reused per etype)
__device__ __align__(16) float g_m[NWORD * NHEAD];       // segment max (local dst idx)
__device__ __align__(16) float g_den[NWORD * NHEAD];     // segment sum of exp

// ---------------- helpers ----------------
__device__ __forceinline__ void atomicMaxFloatBits(int* addr_as_int, float v) {
    if (v >= 0.0f) atomicMax(addr_as_int, __float_as_int(v));
    else           atomicMin((unsigned int*)addr_as_int, __float_as_uint(v));
}

__device__ __forceinline__ void red_add_v4(float* p, float4 v) {
    asm volatile("red.global.add.v4.f32 [%0], {%1, %2, %3, %4};"
                 :: "l"(p), "f"(v.x), "f"(v.y), "f"(v.z), "f"(v.w) : "memory");
}

__device__ __forceinline__ void fma_rank1(float4& acc, float xs, const float4& w) {
    acc.x = fmaf(xs, w.x, acc.x);
    acc.y = fmaf(xs, w.y, acc.y);
    acc.z = fmaf(xs, w.z, acc.z);
    acc.w = fmaf(xs, w.w, acc.w);
}

// ---------------- init kernels ----------------
__global__ void zero_acc_kernel() {
    int i = blockIdx.x * blockDim.x + threadIdx.x;
    if (i < NTOT * (OUTDIM / 4)) ((float4*)g_acc)[i] = make_float4(0.f, 0.f, 0.f, 0.f);
}

__global__ void init_etype_kernel(int nd) {
    int i = blockIdx.x * blockDim.x + threadIdx.x;
    if (i < nd * OUTDIM) g_u[i] = 0.0f;
    if (i < nd * NHEAD) {
        g_m[i] = __int_as_float(0xFF800000);  // -inf
        g_den[i] = 0.0f;
    }
}

// ---------------- k/q/v projection: block = 32 nodes x 128 cols x 3 mats ----------------
__global__ void kqv_kernel(const float* __restrict__ x,
                           const float* __restrict__ Wkp, const float* __restrict__ bkp,
                           const float* __restrict__ Wqp, const float* __restrict__ bqp,
                           const float* __restrict__ Wvp, const float* __restrict__ bvp,
                           int N, int gbase) {
    __shared__ __align__(16) float xs[32 * INDIM];
    int node0 = blockIdx.x * 32;
    int tid = threadIdx.x;

    for (int idx = tid; idx < 32 * INDIM; idx += 256) {
        int r = idx >> 8, c = idx & 255;
        int n = node0 + r;
        xs[idx] = (n < N) ? x[(size_t)n * INDIM + c] : 0.0f;
    }
    __syncthreads();

    int ty = tid >> 5, tx = tid & 31;
    int c0 = tx * 4;       // output column base (0..124)
    int n0 = ty * 4;       // node base within tile (0..28)

    const float* Ws[3] = {Wkp, Wqp, Wvp};
    const float* bs[3] = {bkp, bqp, bvp};
    float* outs[3] = {g_k, g_q, g_v};

#pragma unroll
    for (int m = 0; m < 3; m++) {
        const float* W = Ws[m];
        float4 acc[4];
#pragma unroll
        for (int r = 0; r < 4; r++) acc[r] = make_float4(0.f, 0.f, 0.f, 0.f);

#pragma unroll 4
        for (int kk = 0; kk < INDIM; kk += 4) {
            float4 xv0 = *(const float4*)&xs[(n0 + 0) * INDIM + kk];
            float4 xv1 = *(const float4*)&xs[(n0 + 1) * INDIM + kk];
            float4 xv2 = *(const float4*)&xs[(n0 + 2) * INDIM + kk];
            float4 xv3 = *(const float4*)&xs[(n0 + 3) * INDIM + kk];
            float4 w0 = __ldg((const float4*)&W[(kk + 0) * OUTDIM + c0]);
            float4 w1 = __ldg((const float4*)&W[(kk + 1) * OUTDIM + c0]);
            float4 w2 = __ldg((const float4*)&W[(kk + 2) * OUTDIM + c0]);
            float4 w3 = __ldg((const float4*)&W[(kk + 3) * OUTDIM + c0]);
            fma_rank1(acc[0], xv0.x, w0); fma_rank1(acc[0], xv0.y, w1);
            fma_rank1(acc[0], xv0.z, w2); fma_rank1(acc[0], xv0.w, w3);
            fma_rank1(acc[1], xv1.x, w0); fma_rank1(acc[1], xv1.y, w1);
            fma_rank1(acc[1], xv1.z, w2); fma_rank1(acc[1], xv1.w, w3);
            fma_rank1(acc[2], xv2.x, w0); fma_rank1(acc[2], xv2.y, w1);
            fma_rank1(acc[2], xv2.z, w2); fma_rank1(acc[2], xv2.w, w3);
            fma_rank1(acc[3], xv3.x, w0); fma_rank1(acc[3], xv3.y, w1);
            fma_rank1(acc[3], xv3.z, w2); fma_rank1(acc[3], xv3.w, w3);
        }

        float4 b = __ldg((const float4*)&bs[m][c0]);
        float* outp = outs[m];
#pragma unroll
        for (int r = 0; r < 4; r++) {
            int n = node0 + n0 + r;
            if (n < N) {
                float4 res = acc[r];
                res.x += b.x; res.y += b.y; res.z += b.z; res.w += b.w;
                *(float4*)&outp[(size_t)(gbase + n) * OUTDIM + c0] = res;
            }
        }
    }
}

// ---------------- pass A: att = (q_d . k_s)_h * pri_h / sqrt(dk); segment max ----------------
template <bool TOPIC>
__global__ void passA_kernel(const int* __restrict__ src, const int* __restrict__ dst,
                             const float* __restrict__ pri_e, int sbase, int dbase) {
    __shared__ int ms[TOPIC ? (NTOPIC * NHEAD) : 1];
    if (TOPIC) {
        for (int i = threadIdx.x; i < NTOPIC * NHEAD; i += blockDim.x) ms[i] = 0xFF800000;
        __syncthreads();
    }
    int lane = threadIdx.x & 31;
    int wid = (blockIdx.x * blockDim.x + threadIdx.x) >> 5;
    int nw = (gridDim.x * blockDim.x) >> 5;
    float prih = __ldg(&pri_e[lane >> 2]);

    for (int i = wid; i < NEDGE; i += nw) {
        int s = __ldg(src + i), d = __ldg(dst + i);
        float4 q4 = __ldg((const float4*)(g_q + (size_t)(dbase + d) * OUTDIM) + lane);
        float4 k4 = __ldg((const float4*)(g_k + (size_t)(sbase + s) * OUTDIM) + lane);
        float p = q4.x * k4.x + q4.y * k4.y + q4.z * k4.z + q4.w * k4.w;
        p += __shfl_xor_sync(0xffffffffu, p, 1);
        p += __shfl_xor_sync(0xffffffffu, p, 2);
        if ((lane & 3) == 0) {
            int h = lane >> 2;
            float att = p * prih * 0.25f;   // 1/sqrt(16)
            g_att[(size_t)i * NHEAD + h] = att;
            if (TOPIC) atomicMaxFloatBits(&ms[d * NHEAD + h], att);
            else       atomicMaxFloatBits((int*)&g_m[d * NHEAD + h], att);
        }
    }
    if (TOPIC) {
        __syncthreads();
        for (int i = threadIdx.x; i < NTOPIC * NHEAD; i += blockDim.x)
            atomicMaxFloatBits((int*)&g_m[i], __int_as_float(ms[i]));
    }
}

// ---------------- pass B: ex = exp(att - m); segment sum ----------------
template <bool TOPIC>
__global__ void passB_kernel(const int* __restrict__ dst) {
    __shared__ float ds[TOPIC ? (NTOPIC * NHEAD) : 1];
    if (TOPIC) {
        for (int i = threadIdx.x; i < NTOPIC * NHEAD; i += blockDim.x) ds[i] = 0.0f;
        __syncthreads();
    }
    int tid = blockIdx.x * blockDim.x + threadIdx.x;
    int nth = gridDim.x * blockDim.x;
    for (int idx = tid; idx < NEDGE * NHEAD; idx += nth) {
        int i = idx >> 3, h = idx & 7;
        int d = __ldg(dst + i);
        float ex = __expf(g_att[idx] - g_m[d * NHEAD + h]);
        g_att[idx] = ex;
        if (TOPIC) atomicAdd(&ds[d * NHEAD + h], ex);
        else       atomicAdd(&g_den[d * NHEAD + h], ex);
    }
    if (TOPIC) {
        __syncthreads();
        for (int i = threadIdx.x; i < NTOPIC * NHEAD; i += blockDim.x)
            if (ds[i] != 0.0f) atomicAdd(&g_den[i], ds[i]);
    }
}

// ---------------- pass C: u[d] += (ex/den) * v[s]  (relation bmm deferred) ----------------
template <bool TOPIC>
__global__ void passC_kernel(const int* __restrict__ src, const int* __restrict__ dst, int sbase) {
    __shared__ float us[TOPIC ? (NTOPIC * OUTDIM) : 1];
    if (TOPIC) {
        for (int i = threadIdx.x; i < NTOPIC * OUTDIM; i += blockDim.x) us[i] = 0.0f;
        __syncthreads();
    }
    int lane = threadIdx.x & 31;
    int wid = (blockIdx.x * blockDim.x + threadIdx.x) >> 5;
    int nw = (gridDim.x * blockDim.x) >> 5;
    int h = lane >> 2;

    for (int i = wid; i < NEDGE; i += nw) {
        int s = __ldg(src + i), d = __ldg(dst + i);
        float ex = __ldg(&g_att[(size_t)i * NHEAD + h]);
        float den = __ldg(&g_den[d * NHEAD + h]);
        float w = __fdividef(ex, den);
        float4 v4 = __ldg((const float4*)(g_v + (size_t)(sbase + s) * OUTDIM) + lane);
        v4.x *= w; v4.y *= w; v4.z *= w; v4.w *= w;
        if (TOPIC) {
            float* p = &us[d * OUTDIM + lane * 4];
            atomicAdd(p + 0, v4.x); atomicAdd(p + 1, v4.y);
            atomicAdd(p + 2, v4.z); atomicAdd(p + 3, v4.w);
        } else {
            red_add_v4(&g_u[(size_t)d * OUTDIM + lane * 4], v4);
        }
    }
    if (TOPIC) {
        __syncthreads();
        for (int i = threadIdx.x; i < NTOPIC * OUTDIM; i += blockDim.x)
            if (us[i] != 0.0f) atomicAdd(&g_u[i], us[i]);
    }
}

// ---------------- epilogue: t_acc[dbase+n] += u[n] @ msg[e] (per head 16x16) ----------------
__global__ void epilogue_kernel(const float* __restrict__ msg_e, int dgbase, int nd) {
    int lane = threadIdx.x & 31;
    int h = lane >> 2, j = lane & 3;
    float4 msgr[16];
#pragma unroll
    for (int dd = 0; dd < 16; dd++)
        msgr[dd] = __ldg((const float4*)&msg_e[(h * 16 + dd) * 16 + j * 4]);

    int wid = (blockIdx.x * blockDim.x + threadIdx.x) >> 5;
    int nw = (gridDim.x * blockDim.x) >> 5;
    for (int n = wid; n < nd; n += nw) {
        const float4* up = (const float4*)(g_u + (size_t)n * OUTDIM + h * 16);
        float4 u0 = up[0], u1 = up[1], u2 = up[2], u3 = up[3];
        float uu[16] = {u0.x, u0.y, u0.z, u0.w, u1.x, u1.y, u1.z, u1.w,
                        u2.x, u2.y, u2.z, u2.w, u3.x, u3.y, u3.z, u3.w};
        float4 acc = make_float4(0.f, 0.f, 0.f, 0.f);
#pragma unroll
        for (int dd = 0; dd < 16; dd++) fma_rank1(acc, uu[dd], msgr[dd]);
        float* dp = &g_acc[(size_t)(dgbase + n) * OUTDIM + lane * 4];
        float4 cur = *(const float4*)dp;
        cur.x += acc.x; cur.y += acc.y; cur.z += acc.z; cur.w += acc.w;
        *(float4*)dp = cur;
    }
}

// ---------------- final: relu(acc/dst_count) -> LayerNorm -> gamma/beta ----------------
__global__ void final_kernel(const float* __restrict__ gamma, const float* __restrict__ beta,
                             float* __restrict__ out) {
    int gw = (blockIdx.x * blockDim.x + threadIdx.x) >> 5;
    if (gw >= NTOT) return;
    int lane = threadIdx.x & 31;
    int t = (gw < NWORD) ? 0 : (gw < NWORD + NTOPIC ? 1 : 2);
    float inv = (t == 2) ? 0.5f : (1.0f / 3.0f);

    float4 a = *(const float4*)&g_acc[(size_t)gw * OUTDIM + lane * 4];
    float4 h;
    h.x = fmaxf(a.x * inv, 0.f); h.y = fmaxf(a.y * inv, 0.f);
    h.z = fmaxf(a.z * inv, 0.f); h.w = fmaxf(a.w * inv, 0.f);

    float s = h.x + h.y + h.z + h.w;
#pragma unroll
    for (int o = 16; o; o >>= 1) s += __shfl_xor_sync(0xffffffffu, s, o);
    float mu = s * (1.0f / 128.0f);

    float dx = h.x - mu, dy = h.y - mu, dz = h.z - mu, dw = h.w - mu;
    float ss = dx * dx + dy * dy + dz * dz + dw * dw;
#pragma unroll
    for (int o = 16; o; o >>= 1) ss += __shfl_xor_sync(0xffffffffu, ss, o);
    float rstd = rsqrtf(ss * (1.0f / 128.0f) + 1e-5f);

    float4 g = __ldg((const float4*)&gamma[t * OUTDIM + lane * 4]);
    float4 b = __ldg((const float4*)&beta[t * OUTDIM + lane * 4]);
    float4 o4;
    o4.x = dx * rstd * g.x + b.x;
    o4.y = dy * rstd * g.y + b.y;
    o4.z = dz * rstd * g.z + b.z;
    o4.w = dw * rstd * g.w + b.w;
    *(float4*)&out[(size_t)gw * OUTDIM + lane * 4] = o4;
}

// ---------------- host ----------------
extern "C" void kernel_launch(void* const* d_in, const int* in_sizes, int n_in,
                              void* d_out, int out_size) {
    const float* xs[3] = {(const float*)d_in[0], (const float*)d_in[1], (const float*)d_in[2]};
    const float* Wk = (const float*)d_in[3];
    const float* bk = (const float*)d_in[4];
    const float* Wq = (const float*)d_in[5];
    const float* bq = (const float*)d_in[6];
    const float* Wv = (const float*)d_in[7];
    const float* bv = (const float*)d_in[8];
    const float* pri = (const float*)d_in[9];
    const float* msg = (const float*)d_in[10];
    const float* gamma = (const float*)d_in[11];
    const float* beta = (const float*)d_in[12];
    const int* esrc = (const int*)d_in[13];
    const int* edst = (const int*)d_in[14];
    float* out = (float*)d_out;

    static const int kSrcT[8] = {0, 0, 1, 1, 0, 1, 2, 2};
    static const int kDstT[8] = {1, 2, 2, 1, 0, 0, 1, 0};
    static const int kN[3] = {NWORD, NTOPIC, NDOC};
    static const int kBase[3] = {0, NWORD, NWORD + NTOPIC};

    // zero accumulator
    zero_acc_kernel<<<(NTOT * (OUTDIM / 4) + 255) / 256, 256>>>();

    // k/q/v projections per ntype
    for (int t = 0; t < 3; t++) {
        int nb = (kN[t] + 31) / 32;
        kqv_kernel<<<nb, 256>>>(xs[t],
                                Wk + (size_t)t * INDIM * OUTDIM, bk + t * OUTDIM,
                                Wq + (size_t)t * INDIM * OUTDIM, bq + t * OUTDIM,
                                Wv + (size_t)t * INDIM * OUTDIM, bv + t * OUTDIM,
                                kN[t], kBase[t]);
    }

    for (int e = 0; e < 8; e++) {
        int st = kSrcT[e], dt = kDstT[e];
        int nd = kN[dt];
        int sbase = kBase[st], dbase = kBase[dt];
        const int* se = esrc + (size_t)e * NEDGE;
        const int* de = edst + (size_t)e * NEDGE;
        const float* pe = pri + e * NHEAD;
        const float* me = msg + (size_t)e * NHEAD * DKDIM * DKDIM;
        bool topic = (dt == 1);

        init_etype_kernel<<<(nd * OUTDIM + 255) / 256, 256>>>(nd);

        if (topic) {
            passA_kernel<true><<<592, 256>>>(se, de, pe, sbase, dbase);
            passB_kernel<true><<<592, 256>>>(de);
            passC_kernel<true><<<592, 256>>>(se, de, sbase);
        } else {
            passA_kernel<false><<<(NEDGE + 7) / 8, 256>>>(se, de, pe, sbase, dbase);
            passB_kernel<false><<<(NEDGE * NHEAD + 255) / 256, 256>>>(de);
            passC_kernel<false><<<(NEDGE + 7) / 8, 256>>>(se, de, sbase);
        }
        int eb = (nd + 7) / 8; if (eb > 592) eb = 592;
        epilogue_kernel<<<eb, 256>>>(me, dbase, nd);
    }

    final_kernel<<<(NTOT * 32 + 255) / 256, 256>>>(gamma, beta, out);
}

// round 2
// speedup vs baseline: 1.6810x; 1.6810x over previous
#include <cuda_runtime.h>

#define NWORD  20000
#define NTOPIC 50
#define NDOC   2000
#define NTOT   22050
#define INDIM  256
#define OUTDIM 128
#define NHEAD  8
#define NEDGE  150000
#define UROWS  64150   // sum of dst-node counts over 8 etypes

// ---------------- scratch (device globals) ----------------
__device__ __align__(16) float g_k[NTOT * OUTDIM];
__device__ __align__(16) float g_q[NTOT * OUTDIM];
__device__ __align__(16) float g_v[NTOT * OUTDIM];
__device__ __align__(16) float g_acc[NTOT * OUTDIM];
__device__ __align__(16) float g_att[(size_t)8 * NEDGE * NHEAD];  // 38.4 MB
__device__ __align__(16) float g_u[(size_t)UROWS * OUTDIM];       // 32.8 MB
__device__ __align__(16) float g_m[UROWS * NHEAD];
__device__ __align__(16) float g_den[UROWS * NHEAD];

// per-etype tables
__constant__ int c_sbase[8] = {0, 0, 20000, 20000, 0, 20000, 20050, 20050};
__constant__ int c_dbase[8] = {20000, 20050, 20050, 20000, 0, 0, 20000, 0};
__constant__ int c_nd[8]    = {50, 2000, 2000, 50, 20000, 20000, 50, 20000};
__constant__ int c_uoff[8]  = {0, 50, 2050, 4050, 4100, 24100, 44100, 44150};
__constant__ int c_topic[8] = {1, 0, 0, 1, 0, 0, 1, 0};

#define BPE_A 192
#define BPE_B 128
#define BPE_C 192

// ---------------- helpers ----------------
__device__ __forceinline__ void atomicMaxFloatBits(int* addr_as_int, float v) {
    if (v >= 0.0f) atomicMax(addr_as_int, __float_as_int(v));
    else           atomicMin((unsigned int*)addr_as_int, __float_as_uint(v));
}

__device__ __forceinline__ void red_add_v4(float* p, float4 v) {
    asm volatile("red.global.add.v4.f32 [%0], {%1, %2, %3, %4};"
                 :: "l"(p), "f"(v.x), "f"(v.y), "f"(v.z), "f"(v.w) : "memory");
}

__device__ __forceinline__ void fma_rank1(float4& acc, float xs, const float4& w) {
    acc.x = fmaf(xs, w.x, acc.x);
    acc.y = fmaf(xs, w.y, acc.y);
    acc.z = fmaf(xs, w.z, acc.z);
    acc.w = fmaf(xs, w.w, acc.w);
}

// ---------------- init everything in one launch ----------------
__global__ void init_all_kernel() {
    int tid = blockIdx.x * blockDim.x + threadIdx.x;
    int nth = gridDim.x * blockDim.x;
    float4 z4 = make_float4(0.f, 0.f, 0.f, 0.f);
    float ninf = __int_as_float(0xFF800000);
    float4 n4 = make_float4(ninf, ninf, ninf, ninf);
    for (int i = tid; i < NTOT * OUTDIM / 4; i += nth) ((float4*)g_acc)[i] = z4;
    for (int i = tid; i < UROWS * OUTDIM / 4; i += nth) ((float4*)g_u)[i] = z4;
    for (int i = tid; i < UROWS * NHEAD / 4; i += nth) {
        ((float4*)g_m)[i] = n4;
        ((float4*)g_den)[i] = z4;
    }
}

// ---------------- kqv: grid (690 node-tiles, 3 matrices) ----------------
__global__ void kqv_fused_kernel(const float* __restrict__ xw, const float* __restrict__ xt,
                                 const float* __restrict__ xd,
                                 const float* __restrict__ Wk, const float* __restrict__ bk,
                                 const float* __restrict__ Wq, const float* __restrict__ bq,
                                 const float* __restrict__ Wv, const float* __restrict__ bv) {
    __shared__ __align__(16) float xs[32 * INDIM];
    int bx = blockIdx.x;
    int t, n0, N, gbase;
    const float* x;
    if (bx < 625)      { t = 0; n0 = bx * 32;         N = NWORD;  gbase = 0;      x = xw; }
    else if (bx < 627) { t = 1; n0 = (bx - 625) * 32; N = NTOPIC; gbase = NWORD;  x = xt; }
    else               { t = 2; n0 = (bx - 627) * 32; N = NDOC;   gbase = NWORD + NTOPIC; x = xd; }

    int m = blockIdx.y;
    const float* W = (m == 0 ? Wk : (m == 1 ? Wq : Wv)) + (size_t)t * INDIM * OUTDIM;
    const float* bb = (m == 0 ? bk : (m == 1 ? bq : bv)) + t * OUTDIM;
    float* outp = (m == 0 ? g_k : (m == 1 ? g_q : g_v));

    int tid = threadIdx.x;
    for (int idx = tid; idx < 32 * INDIM; idx += 256) {
        int r = idx >> 8, c = idx & 255;
        int n = n0 + r;
        xs[idx] = (n < N) ? x[(size_t)n * INDIM + c] : 0.0f;
    }
    __syncthreads();

    int ty = tid >> 5, tx = tid & 31;
    int c0 = tx * 4;
    int r0 = ty * 4;

    float4 acc[4];
#pragma unroll
    for (int r = 0; r < 4; r++) acc[r] = make_float4(0.f, 0.f, 0.f, 0.f);

#pragma unroll 4
    for (int kk = 0; kk < INDIM; kk += 4) {
        float4 xv0 = *(const float4*)&xs[(r0 + 0) * INDIM + kk];
        float4 xv1 = *(const float4*)&xs[(r0 + 1) * INDIM + kk];
        float4 xv2 = *(const float4*)&xs[(r0 + 2) * INDIM + kk];
        float4 xv3 = *(const float4*)&xs[(r0 + 3) * INDIM + kk];
        float4 w0 = __ldg((const float4*)&W[(kk + 0) * OUTDIM + c0]);
        float4 w1 = __ldg((const float4*)&W[(kk + 1) * OUTDIM + c0]);
        float4 w2 = __ldg((const float4*)&W[(kk + 2) * OUTDIM + c0]);
        float4 w3 = __ldg((const float4*)&W[(kk + 3) * OUTDIM + c0]);
        fma_rank1(acc[0], xv0.x, w0); fma_rank1(acc[0], xv0.y, w1);
        fma_rank1(acc[0], xv0.z, w2); fma_rank1(acc[0], xv0.w, w3);
        fma_rank1(acc[1], xv1.x, w0); fma_rank1(acc[1], xv1.y, w1);
        fma_rank1(acc[1], xv1.z, w2); fma_rank1(acc[1], xv1.w, w3);
        fma_rank1(acc[2], xv2.x, w0); fma_rank1(acc[2], xv2.y, w1);
        fma_rank1(acc[2], xv2.z, w2); fma_rank1(acc[2], xv2.w, w3);
        fma_rank1(acc[3], xv3.x, w0); fma_rank1(acc[3], xv3.y, w1);
        fma_rank1(acc[3], xv3.z, w2); fma_rank1(acc[3], xv3.w, w3);
    }

    float4 b4 = __ldg((const float4*)&bb[c0]);
#pragma unroll
    for (int r = 0; r < 4; r++) {
        int n = n0 + r0 + r;
        if (n < N) {
            float4 res = acc[r];
            res.x += b4.x; res.y += b4.y; res.z += b4.z; res.w += b4.w;
            *(float4*)&outp[(size_t)(gbase + n) * OUTDIM + c0] = res;
        }
    }
}

// ---------------- pass A (fused over etypes): att + segment max ----------------
__global__ void passA_fused_kernel(const int* __restrict__ esrc, const int* __restrict__ edst,
                                   const float* __restrict__ pri) {
    __shared__ int ms[NTOPIC * NHEAD];
    int e = blockIdx.x / BPE_A;
    int blk = blockIdx.x - e * BPE_A;
    bool topic = c_topic[e];
    if (topic) {
        for (int i = threadIdx.x; i < NTOPIC * NHEAD; i += 256) ms[i] = 0xFF800000;
        __syncthreads();
    }
    const int* src = esrc + (size_t)e * NEDGE;
    const int* dst = edst + (size_t)e * NEDGE;
    float* att = g_att + (size_t)e * NEDGE * NHEAD;
    float* m = g_m + (size_t)c_uoff[e] * NHEAD;
    int sbase = c_sbase[e], dbase = c_dbase[e];

    int lane = threadIdx.x & 31;
    int w = blk * 8 + (threadIdx.x >> 5);
    float prih = __ldg(&pri[e * NHEAD + (lane >> 2)]);

    for (int i = w; i < NEDGE; i += BPE_A * 8) {
        int s = __ldg(src + i), d = __ldg(dst + i);
        float4 q4 = __ldg((const float4*)(g_q + (size_t)(dbase + d) * OUTDIM) + lane);
        float4 k4 = __ldg((const float4*)(g_k + (size_t)(sbase + s) * OUTDIM) + lane);
        float p = q4.x * k4.x + q4.y * k4.y + q4.z * k4.z + q4.w * k4.w;
        p += __shfl_xor_sync(0xffffffffu, p, 1);
        p += __shfl_xor_sync(0xffffffffu, p, 2);
        if ((lane & 3) == 0) {
            int h = lane >> 2;
            float a = p * prih * 0.25f;   // / sqrt(16)
            att[(size_t)i * NHEAD + h] = a;
            if (topic) atomicMaxFloatBits(&ms[d * NHEAD + h], a);
            else       atomicMaxFloatBits((int*)&m[d * NHEAD + h], a);
        }
    }
    if (topic) {
        __syncthreads();
        for (int i = threadIdx.x; i < NTOPIC * NHEAD; i += 256)
            atomicMaxFloatBits((int*)&m[i], __int_as_float(ms[i]));
    }
}

// ---------------- pass B (fused): ex = exp(att - m), segment sum ----------------
__global__ void passB_fused_kernel(const int* __restrict__ edst) {
    __shared__ float ds[NTOPIC * NHEAD];
    int e = blockIdx.x / BPE_B;
    int blk = blockIdx.x - e * BPE_B;
    bool topic = c_topic[e];
    if (topic) {
        for (int i = threadIdx.x; i < NTOPIC * NHEAD; i += 256) ds[i] = 0.0f;
        __syncthreads();
    }
    const int* dst = edst + (size_t)e * NEDGE;
    float* att = g_att + (size_t)e * NEDGE * NHEAD;
    const float* m = g_m + (size_t)c_uoff[e] * NHEAD;
    float* den = g_den + (size_t)c_uoff[e] * NHEAD;

    int t0 = blk * 256 + threadIdx.x;
    for (int idx = t0; idx < NEDGE * NHEAD; idx += BPE_B * 256) {
        int i = idx >> 3, h = idx & 7;
        int d = __ldg(dst + i);
        float ex = __expf(att[idx] - __ldg(&m[d * NHEAD + h]));
        att[idx] = ex;
        if (topic) atomicAdd(&ds[d * NHEAD + h], ex);
        else       atomicAdd(&den[d * NHEAD + h], ex);
    }
    if (topic) {
        __syncthreads();
        for (int i = threadIdx.x; i < NTOPIC * NHEAD; i += 256)
            if (ds[i] != 0.0f) atomicAdd(&den[i], ds[i]);
    }
}

// ---------------- pass C (fused): u[d] += (ex/den) * v[s] ----------------
__global__ void passC_fused_kernel(const int* __restrict__ esrc, const int* __restrict__ edst) {
    __shared__ float us[NTOPIC * OUTDIM];
    int e = blockIdx.x / BPE_C;
    int blk = blockIdx.x - e * BPE_C;
    bool topic = c_topic[e];
    if (topic) {
        for (int i = threadIdx.x; i < NTOPIC * OUTDIM; i += 256) us[i] = 0.0f;
        __syncthreads();
    }
    const int* src = esrc + (size_t)e * NEDGE;
    const int* dst = edst + (size_t)e * NEDGE;
    const float* att = g_att + (size_t)e * NEDGE * NHEAD;
    const float* den = g_den + (size_t)c_uoff[e] * NHEAD;
    float* u = g_u + (size_t)c_uoff[e] * OUTDIM;
    int sbase = c_sbase[e];

    int lane = threadIdx.x & 31;
    int h = lane >> 2;
    int w = blk * 8 + (threadIdx.x >> 5);

    for (int i = w; i < NEDGE; i += BPE_C * 8) {
        int s = __ldg(src + i), d = __ldg(dst + i);
        float ex = __ldg(&att[(size_t)i * NHEAD + h]);
        float dv = __ldg(&den[d * NHEAD + h]);
        float wgt = __fdividef(ex, dv);
        float4 v4 = __ldg((const float4*)(g_v + (size_t)(sbase + s) * OUTDIM) + lane);
        v4.x *= wgt; v4.y *= wgt; v4.z *= wgt; v4.w *= wgt;
        if (topic) {
            float* p = &us[d * OUTDIM + lane * 4];
            atomicAdd(p + 0, v4.x); atomicAdd(p + 1, v4.y);
            atomicAdd(p + 2, v4.z); atomicAdd(p + 3, v4.w);
        } else {
            red_add_v4(&u[(size_t)d * OUTDIM + lane * 4], v4);
        }
    }
    if (topic) {
        __syncthreads();
        for (int i = threadIdx.x; i < NTOPIC * OUTDIM; i += 256)
            if (us[i] != 0.0f) atomicAdd(&u[i], us[i]);
    }
}

// ---------------- epilogue (fused): g_acc[dst] += u @ msg[e] ----------------
__global__ void epilogue_fused_kernel(const float* __restrict__ msg) {
    int e = blockIdx.y;
    int nd = c_nd[e], dbase = c_dbase[e];
    const float* u = g_u + (size_t)c_uoff[e] * OUTDIM;
    const float* msg_e = msg + (size_t)e * NHEAD * 256;

    int lane = threadIdx.x & 31;
    int h = lane >> 2, j = lane & 3;
    float4 msgr[16];
#pragma unroll
    for (int dd = 0; dd < 16; dd++)
        msgr[dd] = __ldg((const float4*)&msg_e[(h * 16 + dd) * 16 + j * 4]);

    int w = (blockIdx.x * blockDim.x + threadIdx.x) >> 5;
    int nw = (gridDim.x * blockDim.x) >> 5;
    for (int n = w; n < nd; n += nw) {
        const float4* up = (const float4*)(u + (size_t)n * OUTDIM + h * 16);
        float4 u0 = up[0], u1 = up[1], u2 = up[2], u3 = up[3];
        float uu[16] = {u0.x, u0.y, u0.z, u0.w, u1.x, u1.y, u1.z, u1.w,
                        u2.x, u2.y, u2.z, u2.w, u3.x, u3.y, u3.z, u3.w};
        float4 acc = make_float4(0.f, 0.f, 0.f, 0.f);
#pragma unroll
        for (int dd = 0; dd < 16; dd++) fma_rank1(acc, uu[dd], msgr[dd]);
        red_add_v4(&g_acc[(size_t)(dbase + n) * OUTDIM + lane * 4], acc);
    }
}

// ---------------- final: relu(acc/cnt) -> LayerNorm ----------------
__global__ void final_kernel(const float* __restrict__ gamma, const float* __restrict__ beta,
                             float* __restrict__ out) {
    int gw = (blockIdx.x * blockDim.x + threadIdx.x) >> 5;
    if (gw >= NTOT) return;
    int lane = threadIdx.x & 31;
    int t = (gw < NWORD) ? 0 : (gw < NWORD + NTOPIC ? 1 : 2);
    float inv = (t == 2) ? 0.5f : (1.0f / 3.0f);

    float4 a = *(const float4*)&g_acc[(size_t)gw * OUTDIM + lane * 4];
    float4 h;
    h.x = fmaxf(a.x * inv, 0.f); h.y = fmaxf(a.y * inv, 0.f);
    h.z = fmaxf(a.z * inv, 0.f); h.w = fmaxf(a.w * inv, 0.f);

    float s = h.x + h.y + h.z + h.w;
#pragma unroll
    for (int o = 16; o; o >>= 1) s += __shfl_xor_sync(0xffffffffu, s, o);
    float mu = s * (1.0f / 128.0f);

    float dx = h.x - mu, dy = h.y - mu, dz = h.z - mu, dw = h.w - mu;
    float ss = dx * dx + dy * dy + dz * dz + dw * dw;
#pragma unroll
    for (int o = 16; o; o >>= 1) ss += __shfl_xor_sync(0xffffffffu, ss, o);
    float rstd = rsqrtf(ss * (1.0f / 128.0f) + 1e-5f);

    float4 g = __ldg((const float4*)&gamma[t * OUTDIM + lane * 4]);
    float4 b = __ldg((const float4*)&beta[t * OUTDIM + lane * 4]);
    float4 o4;
    o4.x = dx * rstd * g.x + b.x;
    o4.y = dy * rstd * g.y + b.y;
    o4.z = dz * rstd * g.z + b.z;
    o4.w = dw * rstd * g.w + b.w;
    *(float4*)&out[(size_t)gw * OUTDIM + lane * 4] = o4;
}

// ---------------- host ----------------
extern "C" void kernel_launch(void* const* d_in, const int* in_sizes, int n_in,
                              void* d_out, int out_size) {
    const float* xw = (const float*)d_in[0];
    const float* xt = (const float*)d_in[1];
    const float* xd = (const float*)d_in[2];
    const float* Wk = (const float*)d_in[3];
    const float* bk = (const float*)d_in[4];
    const float* Wq = (const float*)d_in[5];
    const float* bq = (const float*)d_in[6];
    const float* Wv = (const float*)d_in[7];
    const float* bv = (const float*)d_in[8];
    const float* pri = (const float*)d_in[9];
    const float* msg = (const float*)d_in[10];
    const float* gamma = (const float*)d_in[11];
    const float* beta = (const float*)d_in[12];
    const int* esrc = (const int*)d_in[13];
    const int* edst = (const int*)d_in[14];
    float* out = (float*)d_out;

    init_all_kernel<<<1184, 256>>>();

    dim3 kqv_grid(690, 3);
    kqv_fused_kernel<<<kqv_grid, 256>>>(xw, xt, xd, Wk, bk, Wq, bq, Wv, bv);

    passA_fused_kernel<<<8 * BPE_A, 256>>>(esrc, edst, pri);
    passB_fused_kernel<<<8 * BPE_B, 256>>>(edst);
    passC_fused_kernel<<<8 * BPE_C, 256>>>(esrc, edst);

    dim3 epi_grid(80, 8);
    epilogue_fused_kernel<<<epi_grid, 256>>>(msg);

    final_kernel<<<(NTOT * 32 + 255) / 256, 256>>>(gamma, beta, out);
}

// round 3
// speedup vs baseline: 2.2315x; 1.3275x over previous
#include <cuda_runtime.h>

#define NWORD  20000
#define NTOPIC 50
#define NDOC   2000
#define NTOT   22050
#define INDIM  256
#define OUTDIM 128
#define NHEAD  8
#define NEDGE  150000
#define UROWS  64150   // sum of dst-node counts over 8 etypes

// ---------------- scratch (device globals) ----------------
__device__ __align__(16) float g_k[NTOT * OUTDIM];
__device__ __align__(16) float g_q[NTOT * OUTDIM];
__device__ __align__(16) float g_v[NTOT * OUTDIM];
__device__ __align__(16) float g_acc[NTOT * OUTDIM];
__device__ __align__(16) float g_u[(size_t)UROWS * OUTDIM];   // unnormalized sum(ex*v)
__device__ __align__(16) float g_den[UROWS * NHEAD];          // sum(ex)

// per-etype tables
__constant__ int c_sbase[8] = {0, 0, 20000, 20000, 0, 20000, 20050, 20050};
__constant__ int c_dbase[8] = {20000, 20050, 20050, 20000, 0, 0, 20000, 0};
__constant__ int c_nd[8]    = {50, 2000, 2000, 50, 20000, 20000, 50, 20000};
__constant__ int c_uoff[8]  = {0, 50, 2050, 4050, 4100, 24100, 44100, 44150};
__constant__ int c_topic[8] = {1, 0, 0, 1, 0, 0, 1, 0};

#define BPE 148   // blocks per etype for the edge pass (1 full wave total)

// ---------------- helpers ----------------
__device__ __forceinline__ void red_add_v4(float* p, float4 v) {
    asm volatile("red.global.add.v4.f32 [%0], {%1, %2, %3, %4};"
                 :: "l"(p), "f"(v.x), "f"(v.y), "f"(v.z), "f"(v.w) : "memory");
}

__device__ __forceinline__ void red_add_f32(float* p, float v) {
    asm volatile("red.global.add.f32 [%0], %1;" :: "l"(p), "f"(v) : "memory");
}

__device__ __forceinline__ void fma_rank1(float4& acc, float xs, const float4& w) {
    acc.x = fmaf(xs, w.x, acc.x);
    acc.y = fmaf(xs, w.y, acc.y);
    acc.z = fmaf(xs, w.z, acc.z);
    acc.w = fmaf(xs, w.w, acc.w);
}

// ---------------- init everything in one launch ----------------
__global__ void init_all_kernel() {
    int tid = blockIdx.x * blockDim.x + threadIdx.x;
    int nth = gridDim.x * blockDim.x;
    float4 z4 = make_float4(0.f, 0.f, 0.f, 0.f);
    for (int i = tid; i < NTOT * OUTDIM / 4; i += nth) ((float4*)g_acc)[i] = z4;
    for (size_t i = tid; i < (size_t)UROWS * OUTDIM / 4; i += nth) ((float4*)g_u)[i] = z4;
    for (int i = tid; i < UROWS * NHEAD / 4; i += nth) ((float4*)g_den)[i] = z4;
}

// ---------------- kqv: grid (690 node-tiles, 3 matrices) ----------------
__global__ void kqv_fused_kernel(const float* __restrict__ xw, const float* __restrict__ xt,
                                 const float* __restrict__ xd,
                                 const float* __restrict__ Wk, const float* __restrict__ bk,
                                 const float* __restrict__ Wq, const float* __restrict__ bq,
                                 const float* __restrict__ Wv, const float* __restrict__ bv) {
    __shared__ __align__(16) float xs[32 * INDIM];
    int bx = blockIdx.x;
    int t, n0, N, gbase;
    const float* x;
    if (bx < 625)      { t = 0; n0 = bx * 32;         N = NWORD;  gbase = 0;      x = xw; }
    else if (bx < 627) { t = 1; n0 = (bx - 625) * 32; N = NTOPIC; gbase = NWORD;  x = xt; }
    else               { t = 2; n0 = (bx - 627) * 32; N = NDOC;   gbase = NWORD + NTOPIC; x = xd; }

    int m = blockIdx.y;
    const float* W = (m == 0 ? Wk : (m == 1 ? Wq : Wv)) + (size_t)t * INDIM * OUTDIM;
    const float* bb = (m == 0 ? bk : (m == 1 ? bq : bv)) + t * OUTDIM;
    float* outp = (m == 0 ? g_k : (m == 1 ? g_q : g_v));

    int tid = threadIdx.x;
    for (int idx = tid; idx < 32 * INDIM; idx += 256) {
        int r = idx >> 8, c = idx & 255;
        int n = n0 + r;
        xs[idx] = (n < N) ? x[(size_t)n * INDIM + c] : 0.0f;
    }
    __syncthreads();

    int ty = tid >> 5, tx = tid & 31;
    int c0 = tx * 4;
    int r0 = ty * 4;

    float4 acc[4];
#pragma unroll
    for (int r = 0; r < 4; r++) acc[r] = make_float4(0.f, 0.f, 0.f, 0.f);

#pragma unroll 4
    for (int kk = 0; kk < INDIM; kk += 4) {
        float4 xv0 = *(const float4*)&xs[(r0 + 0) * INDIM + kk];
        float4 xv1 = *(const float4*)&xs[(r0 + 1) * INDIM + kk];
        float4 xv2 = *(const float4*)&xs[(r0 + 2) * INDIM + kk];
        float4 xv3 = *(const float4*)&xs[(r0 + 3) * INDIM + kk];
        float4 w0 = __ldg((const float4*)&W[(kk + 0) * OUTDIM + c0]);
        float4 w1 = __ldg((const float4*)&W[(kk + 1) * OUTDIM + c0]);
        float4 w2 = __ldg((const float4*)&W[(kk + 2) * OUTDIM + c0]);
        float4 w3 = __ldg((const float4*)&W[(kk + 3) * OUTDIM + c0]);
        fma_rank1(acc[0], xv0.x, w0); fma_rank1(acc[0], xv0.y, w1);
        fma_rank1(acc[0], xv0.z, w2); fma_rank1(acc[0], xv0.w, w3);
        fma_rank1(acc[1], xv1.x, w0); fma_rank1(acc[1], xv1.y, w1);
        fma_rank1(acc[1], xv1.z, w2); fma_rank1(acc[1], xv1.w, w3);
        fma_rank1(acc[2], xv2.x, w0); fma_rank1(acc[2], xv2.y, w1);
        fma_rank1(acc[2], xv2.z, w2); fma_rank1(acc[2], xv2.w, w3);
        fma_rank1(acc[3], xv3.x, w0); fma_rank1(acc[3], xv3.y, w1);
        fma_rank1(acc[3], xv3.z, w2); fma_rank1(acc[3], xv3.w, w3);
    }

    float4 b4 = __ldg((const float4*)&bb[c0]);
#pragma unroll
    for (int r = 0; r < 4; r++) {
        int n = n0 + r0 + r;
        if (n < N) {
            float4 res = acc[r];
            res.x += b4.x; res.y += b4.y; res.z += b4.z; res.w += b4.w;
            *(float4*)&outp[(size_t)(gbase + n) * OUTDIM + c0] = res;
        }
    }
}

// ---------------- single fused edge pass: u[d] += exp(att)*v[s]; den[d] += exp(att) ----------------
__global__ void edge_fused_kernel(const int* __restrict__ esrc, const int* __restrict__ edst,
                                  const float* __restrict__ pri) {
    __shared__ float us[NTOPIC * OUTDIM];   // 25.6 KB
    __shared__ float ds[NTOPIC * NHEAD];    // 1.6 KB
    int e = blockIdx.x / BPE;
    int blk = blockIdx.x - e * BPE;
    bool topic = c_topic[e];
    if (topic) {
        for (int i = threadIdx.x; i < NTOPIC * OUTDIM; i += 256) us[i] = 0.0f;
        for (int i = threadIdx.x; i < NTOPIC * NHEAD; i += 256) ds[i] = 0.0f;
        __syncthreads();
    }
    const int* src = esrc + (size_t)e * NEDGE;
    const int* dst = edst + (size_t)e * NEDGE;
    float* u = g_u + (size_t)c_uoff[e] * OUTDIM;
    float* den = g_den + (size_t)c_uoff[e] * NHEAD;
    int sbase = c_sbase[e], dbase = c_dbase[e];

    int lane = threadIdx.x & 31;
    int h = lane >> 2;
    int w = blk * 8 + (threadIdx.x >> 5);
    float prih = __ldg(&pri[e * NHEAD + h]) * 0.25f;   // fold 1/sqrt(16)

    for (int i = w; i < NEDGE; i += BPE * 8) {
        int s = __ldg(src + i), d = __ldg(dst + i);
        float4 q4 = __ldg((const float4*)(g_q + (size_t)(dbase + d) * OUTDIM) + lane);
        float4 k4 = __ldg((const float4*)(g_k + (size_t)(sbase + s) * OUTDIM) + lane);
        float p = q4.x * k4.x + q4.y * k4.y + q4.z * k4.z + q4.w * k4.w;
        p += __shfl_xor_sync(0xffffffffu, p, 1);
        p += __shfl_xor_sync(0xffffffffu, p, 2);
        float ex = __expf(p * prih);           // no max-shift: |att| <~ 6, safe
        float4 v4 = __ldg((const float4*)(g_v + (size_t)(sbase + s) * OUTDIM) + lane);
        v4.x *= ex; v4.y *= ex; v4.z *= ex; v4.w *= ex;
        if (topic) {
            float* pp = &us[d * OUTDIM + lane * 4];
            atomicAdd(pp + 0, v4.x); atomicAdd(pp + 1, v4.y);
            atomicAdd(pp + 2, v4.z); atomicAdd(pp + 3, v4.w);
            if ((lane & 3) == 0) atomicAdd(&ds[d * NHEAD + h], ex);
        } else {
            red_add_v4(&u[(size_t)d * OUTDIM + lane * 4], v4);
            if ((lane & 3) == 0) red_add_f32(&den[d * NHEAD + h], ex);
        }
    }
    if (topic) {
        __syncthreads();
        for (int i = threadIdx.x; i < NTOPIC * OUTDIM; i += 256)
            if (us[i] != 0.0f) red_add_f32(&u[i], us[i]);
        for (int i = threadIdx.x; i < NTOPIC * NHEAD; i += 256)
            if (ds[i] != 0.0f) red_add_f32(&den[i], ds[i]);
    }
}

// ---------------- epilogue (fused): g_acc[dst] += (u/den) @ msg[e] ----------------
__global__ void epilogue_fused_kernel(const float* __restrict__ msg) {
    int e = blockIdx.y;
    int nd = c_nd[e], dbase = c_dbase[e];
    const float* u = g_u + (size_t)c_uoff[e] * OUTDIM;
    const float* den = g_den + (size_t)c_uoff[e] * NHEAD;
    const float* msg_e = msg + (size_t)e * NHEAD * 256;

    int lane = threadIdx.x & 31;
    int h = lane >> 2, j = lane & 3;
    float4 msgr[16];
#pragma unroll
    for (int dd = 0; dd < 16; dd++)
        msgr[dd] = __ldg((const float4*)&msg_e[(h * 16 + dd) * 16 + j * 4]);

    int w = (blockIdx.x * blockDim.x + threadIdx.x) >> 5;
    int nw = (gridDim.x * blockDim.x) >> 5;
    for (int n = w; n < nd; n += nw) {
        float dv = __ldg(&den[n * NHEAD + h]);
        float inv = (dv > 0.0f) ? __fdividef(1.0f, dv) : 0.0f;  // no-edge nodes -> 0
        const float4* up = (const float4*)(u + (size_t)n * OUTDIM + h * 16);
        float4 u0 = up[0], u1 = up[1], u2 = up[2], u3 = up[3];
        float uu[16] = {u0.x * inv, u0.y * inv, u0.z * inv, u0.w * inv,
                        u1.x * inv, u1.y * inv, u1.z * inv, u1.w * inv,
                        u2.x * inv, u2.y * inv, u2.z * inv, u2.w * inv,
                        u3.x * inv, u3.y * inv, u3.z * inv, u3.w * inv};
        float4 acc = make_float4(0.f, 0.f, 0.f, 0.f);
#pragma unroll
        for (int dd = 0; dd < 16; dd++) fma_rank1(acc, uu[dd], msgr[dd]);
        red_add_v4(&g_acc[(size_t)(dbase + n) * OUTDIM + lane * 4], acc);
    }
}

// ---------------- final: relu(acc/cnt) -> LayerNorm ----------------
__global__ void final_kernel(const float* __restrict__ gamma, const float* __restrict__ beta,
                             float* __restrict__ out) {
    int gw = (blockIdx.x * blockDim.x + threadIdx.x) >> 5;
    if (gw >= NTOT) return;
    int lane = threadIdx.x & 31;
    int t = (gw < NWORD) ? 0 : (gw < NWORD + NTOPIC ? 1 : 2);
    float inv = (t == 2) ? 0.5f : (1.0f / 3.0f);

    float4 a = *(const float4*)&g_acc[(size_t)gw * OUTDIM + lane * 4];
    float4 h;
    h.x = fmaxf(a.x * inv, 0.f); h.y = fmaxf(a.y * inv, 0.f);
    h.z = fmaxf(a.z * inv, 0.f); h.w = fmaxf(a.w * inv, 0.f);

    float s = h.x + h.y + h.z + h.w;
#pragma unroll
    for (int o = 16; o; o >>= 1) s += __shfl_xor_sync(0xffffffffu, s, o);
    float mu = s * (1.0f / 128.0f);

    float dx = h.x - mu, dy = h.y - mu, dz = h.z - mu, dw = h.w - mu;
    float ss = dx * dx + dy * dy + dz * dz + dw * dw;
#pragma unroll
    for (int o = 16; o; o >>= 1) ss += __shfl_xor_sync(0xffffffffu, ss, o);
    float rstd = rsqrtf(ss * (1.0f / 128.0f) + 1e-5f);

    float4 g = __ldg((const float4*)&gamma[t * OUTDIM + lane * 4]);
    float4 b = __ldg((const float4*)&beta[t * OUTDIM + lane * 4]);
    float4 o4;
    o4.x = dx * rstd * g.x + b.x;
    o4.y = dy * rstd * g.y + b.y;
    o4.z = dz * rstd * g.z + b.z;
    o4.w = dw * rstd * g.w + b.w;
    *(float4*)&out[(size_t)gw * OUTDIM + lane * 4] = o4;
}

// ---------------- host ----------------
extern "C" void kernel_launch(void* const* d_in, const int* in_sizes, int n_in,
                              void* d_out, int out_size) {
    const float* xw = (const float*)d_in[0];
    const float* xt = (const float*)d_in[1];
    const float* xd = (const float*)d_in[2];
    const float* Wk = (const float*)d_in[3];
    const float* bk = (const float*)d_in[4];
    const float* Wq = (const float*)d_in[5];
    const float* bq = (const float*)d_in[6];
    const float* Wv = (const float*)d_in[7];
    const float* bv = (const float*)d_in[8];
    const float* pri = (const float*)d_in[9];
    const float* msg = (const float*)d_in[10];
    const float* gamma = (const float*)d_in[11];
    const float* beta = (const float*)d_in[12];
    const int* esrc = (const int*)d_in[13];
    const int* edst = (const int*)d_in[14];
    float* out = (float*)d_out;

    init_all_kernel<<<1184, 256>>>();

    dim3 kqv_grid(690, 3);
    kqv_fused_kernel<<<kqv_grid, 256>>>(xw, xt, xd, Wk, bk, Wq, bq, Wv, bv);

    edge_fused_kernel<<<8 * BPE, 256>>>(esrc, edst, pri);

    dim3 epi_grid(148, 8);
    epilogue_fused_kernel<<<epi_grid, 256>>>(msg);

    final_kernel<<<(NTOT * 32 + 255) / 256, 256>>>(gamma, beta, out);
}

// round 4
// speedup vs baseline: 2.2468x; 1.0069x over previous
#include <cuda_runtime.h>

#define NWORD  20000
#define NTOPIC 50
#define NDOC   2000
#define NTOT   22050
#define INDIM  256
#define OUTDIM 128
#define NHEAD  8
#define NEDGE  150000
#define UROWS  64150

// ---------------- scratch ----------------
__device__ __align__(16) float g_k[NTOT * OUTDIM];
__device__ __align__(16) float g_q[NTOT * OUTDIM];
__device__ __align__(16) float g_v[NTOT * OUTDIM];
__device__ __align__(16) float g_u[(size_t)UROWS * OUTDIM];   // unnormalized sum(ex*v)
__device__ __align__(16) float g_den[UROWS * NHEAD];          // sum(ex)

// per-etype tables
__constant__ int c_sbase[8] = {0, 0, 20000, 20000, 0, 20000, 20050, 20050};
__constant__ int c_dbase[8] = {20000, 20050, 20050, 20000, 0, 0, 20000, 0};
__constant__ int c_uoff[8]  = {0, 50, 2050, 4050, 4100, 24100, 44100, 44150};
__constant__ int c_topic[8] = {1, 0, 0, 1, 0, 0, 1, 0};
// etypes delivering to each ntype (dst lists)
__constant__ int c_elist[3][3] = {{4, 5, 7}, {0, 3, 6}, {1, 2, 0}};
__constant__ int c_nel[3] = {3, 3, 2};

#define BPE 148
#define NWRP (BPE * 8)

// ---------------- helpers ----------------
__device__ __forceinline__ void ffma2(unsigned long long& d, unsigned long long a,
                                      unsigned long long b) {
    asm("fma.rn.f32x2 %0, %1, %2, %0;" : "+l"(d) : "l"(a), "l"(b));
}
__device__ __forceinline__ unsigned long long pack2(float x) {
    unsigned long long r;
    asm("mov.b64 %0, {%1, %1};" : "=l"(r) : "f"(x));
    return r;
}
__device__ __forceinline__ float2 unpack2(unsigned long long v) {
    float2 f;
    asm("mov.b64 {%0, %1}, %2;" : "=f"(f.x), "=f"(f.y) : "l"(v));
    return f;
}
__device__ __forceinline__ void red_add_v4(float* p, float4 v) {
    asm volatile("red.global.add.v4.f32 [%0], {%1, %2, %3, %4};"
                 :: "l"(p), "f"(v.x), "f"(v.y), "f"(v.z), "f"(v.w) : "memory");
}
__device__ __forceinline__ void red_add_f32(float* p, float v) {
    asm volatile("red.global.add.f32 [%0], %1;" :: "l"(p), "f"(v) : "memory");
}

// ---------------- init: zero u and den ----------------
__global__ void init_all_kernel() {
    int tid = blockIdx.x * blockDim.x + threadIdx.x;
    int nth = gridDim.x * blockDim.x;
    float4 z4 = make_float4(0.f, 0.f, 0.f, 0.f);
    for (size_t i = tid; i < (size_t)UROWS * OUTDIM / 4; i += nth) ((float4*)g_u)[i] = z4;
    for (int i = tid; i < UROWS * NHEAD / 4; i += nth) ((float4*)g_den)[i] = z4;
}

// ---------------- kqv (FFMA2): grid (690 node-tiles, 3 matrices) ----------------
__global__ void kqv_fused_kernel(const float* __restrict__ xw, const float* __restrict__ xt,
                                 const float* __restrict__ xd,
                                 const float* __restrict__ Wk, const float* __restrict__ bk,
                                 const float* __restrict__ Wq, const float* __restrict__ bq,
                                 const float* __restrict__ Wv, const float* __restrict__ bv) {
    __shared__ __align__(16) float xs[32 * INDIM];
    int bx = blockIdx.x;
    int t, n0, N, gbase;
    const float* x;
    if (bx < 625)      { t = 0; n0 = bx * 32;         N = NWORD;  gbase = 0;      x = xw; }
    else if (bx < 627) { t = 1; n0 = (bx - 625) * 32; N = NTOPIC; gbase = NWORD;  x = xt; }
    else               { t = 2; n0 = (bx - 627) * 32; N = NDOC;   gbase = NWORD + NTOPIC; x = xd; }

    int m = blockIdx.y;
    const float* W = (m == 0 ? Wk : (m == 1 ? Wq : Wv)) + (size_t)t * INDIM * OUTDIM;
    const float* bb = (m == 0 ? bk : (m == 1 ? bq : bv)) + t * OUTDIM;
    float* outp = (m == 0 ? g_k : (m == 1 ? g_q : g_v));

    int tid = threadIdx.x;
    for (int idx = tid; idx < 32 * INDIM; idx += 256) {
        int r = idx >> 8, c = idx & 255;
        int n = n0 + r;
        xs[idx] = (n < N) ? x[(size_t)n * INDIM + c] : 0.0f;
    }
    __syncthreads();

    int ty = tid >> 5, tx = tid & 31;
    int c0 = tx * 4;
    int r0 = ty * 4;

    unsigned long long acc2[4][2];
#pragma unroll
    for (int r = 0; r < 4; r++) { acc2[r][0] = 0ull; acc2[r][1] = 0ull; }

#pragma unroll 4
    for (int kk = 0; kk < INDIM; kk += 4) {
        float4 xv0 = *(const float4*)&xs[(r0 + 0) * INDIM + kk];
        float4 xv1 = *(const float4*)&xs[(r0 + 1) * INDIM + kk];
        float4 xv2 = *(const float4*)&xs[(r0 + 2) * INDIM + kk];
        float4 xv3 = *(const float4*)&xs[(r0 + 3) * INDIM + kk];
        ulonglong2 w0 = __ldg((const ulonglong2*)&W[(kk + 0) * OUTDIM + c0]);
        ulonglong2 w1 = __ldg((const ulonglong2*)&W[(kk + 1) * OUTDIM + c0]);
        ulonglong2 w2 = __ldg((const ulonglong2*)&W[(kk + 2) * OUTDIM + c0]);
        ulonglong2 w3 = __ldg((const ulonglong2*)&W[(kk + 3) * OUTDIM + c0]);
#pragma unroll
        for (int r = 0; r < 4; r++) {
            float4 xv = (r == 0) ? xv0 : (r == 1) ? xv1 : (r == 2) ? xv2 : xv3;
            unsigned long long p0 = pack2(xv.x);
            ffma2(acc2[r][0], p0, w0.x); ffma2(acc2[r][1], p0, w0.y);
            unsigned long long p1 = pack2(xv.y);
            ffma2(acc2[r][0], p1, w1.x); ffma2(acc2[r][1], p1, w1.y);
            unsigned long long p2 = pack2(xv.z);
            ffma2(acc2[r][0], p2, w2.x); ffma2(acc2[r][1], p2, w2.y);
            unsigned long long p3 = pack2(xv.w);
            ffma2(acc2[r][0], p3, w3.x); ffma2(acc2[r][1], p3, w3.y);
        }
    }

    float4 b4 = __ldg((const float4*)&bb[c0]);
#pragma unroll
    for (int r = 0; r < 4; r++) {
        int n = n0 + r0 + r;
        if (n < N) {
            float2 lo = unpack2(acc2[r][0]);
            float2 hi = unpack2(acc2[r][1]);
            float4 res;
            res.x = lo.x + b4.x; res.y = lo.y + b4.y;
            res.z = hi.x + b4.z; res.w = hi.y + b4.w;
            *(float4*)&outp[(size_t)(gbase + n) * OUTDIM + c0] = res;
        }
    }
}

// ---------------- fused edge pass, unroll x4 ----------------
__global__ void __launch_bounds__(256, 3)
edge_fused_kernel(const int* __restrict__ esrc, const int* __restrict__ edst,
                  const float* __restrict__ pri) {
    __shared__ float us[NTOPIC * OUTDIM];   // 25.6 KB
    __shared__ float ds[NTOPIC * NHEAD];    // 1.6 KB
    int e = blockIdx.x / BPE;
    int blk = blockIdx.x - e * BPE;
    bool topic = c_topic[e];
    if (topic) {
        for (int i = threadIdx.x; i < NTOPIC * OUTDIM; i += 256) us[i] = 0.0f;
        for (int i = threadIdx.x; i < NTOPIC * NHEAD; i += 256) ds[i] = 0.0f;
        __syncthreads();
    }
    const int* src = esrc + (size_t)e * NEDGE;
    const int* dst = edst + (size_t)e * NEDGE;
    float* u = g_u + (size_t)c_uoff[e] * OUTDIM;
    float* den = g_den + (size_t)c_uoff[e] * NHEAD;
    int sbase = c_sbase[e], dbase = c_dbase[e];

    int lane = threadIdx.x & 31;
    int h = lane >> 2;
    int w = blk * 8 + (threadIdx.x >> 5);
    float prih = __ldg(&pri[e * NHEAD + h]) * 0.25f;

    for (int base = w; base < NEDGE; base += NWRP * 4) {
        int ss[4], dd[4];
        bool act[4];
        float4 q4[4], k4[4], v4[4];
#pragma unroll
        for (int j = 0; j < 4; j++) {
            int i = base + j * NWRP;
            act[j] = (i < NEDGE);
            if (act[j]) { ss[j] = __ldg(src + i); dd[j] = __ldg(dst + i); }
        }
#pragma unroll
        for (int j = 0; j < 4; j++) {
            if (act[j]) {
                q4[j] = __ldg((const float4*)(g_q + (size_t)(dbase + dd[j]) * OUTDIM) + lane);
                k4[j] = __ldg((const float4*)(g_k + (size_t)(sbase + ss[j]) * OUTDIM) + lane);
                v4[j] = __ldg((const float4*)(g_v + (size_t)(sbase + ss[j]) * OUTDIM) + lane);
            }
        }
#pragma unroll
        for (int j = 0; j < 4; j++) {
            if (act[j]) {
                float p = q4[j].x * k4[j].x + q4[j].y * k4[j].y +
                          q4[j].z * k4[j].z + q4[j].w * k4[j].w;
                p += __shfl_xor_sync(0xffffffffu, p, 1);
                p += __shfl_xor_sync(0xffffffffu, p, 2);
                float ex = __expf(p * prih);
                float4 vv = v4[j];
                vv.x *= ex; vv.y *= ex; vv.z *= ex; vv.w *= ex;
                int d = dd[j];
                if (topic) {
                    float* pp = &us[d * OUTDIM + lane * 4];
                    atomicAdd(pp + 0, vv.x); atomicAdd(pp + 1, vv.y);
                    atomicAdd(pp + 2, vv.z); atomicAdd(pp + 3, vv.w);
                    if ((lane & 3) == 0) atomicAdd(&ds[d * NHEAD + h], ex);
                } else {
                    red_add_v4(&u[(size_t)d * OUTDIM + lane * 4], vv);
                    if ((lane & 3) == 0) red_add_f32(&den[d * NHEAD + h], ex);
                }
            }
        }
    }
    if (topic) {
        __syncthreads();
        for (int i = threadIdx.x; i < NTOPIC * OUTDIM; i += 256)
            if (us[i] != 0.0f) red_add_f32(&u[i], us[i]);
        for (int i = threadIdx.x; i < NTOPIC * NHEAD; i += 256)
            if (ds[i] != 0.0f) red_add_f32(&den[i], ds[i]);
    }
}

// ---------------- fused epilogue + final: normalize, bmm, mean, relu, LN ----------------
__global__ void final_fused_kernel(const float* __restrict__ msg,
                                   const float* __restrict__ gamma,
                                   const float* __restrict__ beta,
                                   float* __restrict__ out) {
    int gw = (blockIdx.x * blockDim.x + threadIdx.x) >> 5;
    if (gw >= NTOT) return;
    int lane = threadIdx.x & 31;
    int h = lane >> 2, j = lane & 3;

    int t, n;
    if (gw < NWORD)              { t = 0; n = gw; }
    else if (gw < NWORD + NTOPIC){ t = 1; n = gw - NWORD; }
    else                         { t = 2; n = gw - NWORD - NTOPIC; }
    int nel = c_nel[t];

    unsigned long long acc2[2] = {0ull, 0ull};
#pragma unroll 3
    for (int ei = 0; ei < 3; ei++) {
        if (ei >= nel) break;
        int e = c_elist[t][ei];
        size_t row = (size_t)(c_uoff[e] + n);
        float dv = __ldg(&g_den[row * NHEAD + h]);
        float inv = (dv > 0.0f) ? __fdividef(1.0f, dv) : 0.0f;
        const float4* up = (const float4*)(g_u + row * OUTDIM + h * 16);
        float4 u0 = up[0], u1 = up[1], u2 = up[2], u3 = up[3];
        float uu[16] = {u0.x * inv, u0.y * inv, u0.z * inv, u0.w * inv,
                        u1.x * inv, u1.y * inv, u1.z * inv, u1.w * inv,
                        u2.x * inv, u2.y * inv, u2.z * inv, u2.w * inv,
                        u3.x * inv, u3.y * inv, u3.z * inv, u3.w * inv};
        const float* msg_e = msg + (size_t)e * NHEAD * 256;
#pragma unroll
        for (int dd = 0; dd < 16; dd++) {
            ulonglong2 mv = __ldg((const ulonglong2*)&msg_e[(h * 16 + dd) * 16 + j * 4]);
            unsigned long long sb = pack2(uu[dd]);
            ffma2(acc2[0], sb, mv.x);
            ffma2(acc2[1], sb, mv.y);
        }
    }

    float invc = (t == 2) ? 0.5f : (1.0f / 3.0f);
    float2 a01 = unpack2(acc2[0]);
    float2 a23 = unpack2(acc2[1]);
    float4 hh;
    hh.x = fmaxf(a01.x * invc, 0.f); hh.y = fmaxf(a01.y * invc, 0.f);
    hh.z = fmaxf(a23.x * invc, 0.f); hh.w = fmaxf(a23.y * invc, 0.f);

    float s = hh.x + hh.y + hh.z + hh.w;
#pragma unroll
    for (int o = 16; o; o >>= 1) s += __shfl_xor_sync(0xffffffffu, s, o);
    float mu = s * (1.0f / 128.0f);

    float dx = hh.x - mu, dy = hh.y - mu, dz = hh.z - mu, dw = hh.w - mu;
    float ssq = dx * dx + dy * dy + dz * dz + dw * dw;
#pragma unroll
    for (int o = 16; o; o >>= 1) ssq += __shfl_xor_sync(0xffffffffu, ssq, o);
    float rstd = rsqrtf(ssq * (1.0f / 128.0f) + 1e-5f);

    float4 g = __ldg((const float4*)&gamma[t * OUTDIM + lane * 4]);
    float4 b = __ldg((const float4*)&beta[t * OUTDIM + lane * 4]);
    float4 o4;
    o4.x = dx * rstd * g.x + b.x;
    o4.y = dy * rstd * g.y + b.y;
    o4.z = dz * rstd * g.z + b.z;
    o4.w = dw * rstd * g.w + b.w;
    *(float4*)&out[(size_t)gw * OUTDIM + lane * 4] = o4;
}

// ---------------- host ----------------
extern "C" void kernel_launch(void* const* d_in, const int* in_sizes, int n_in,
                              void* d_out, int out_size) {
    const float* xw = (const float*)d_in[0];
    const float* xt = (const float*)d_in[1];
    const float* xd = (const float*)d_in[2];
    const float* Wk = (const float*)d_in[3];
    const float* bk = (const float*)d_in[4];
    const float* Wq = (const float*)d_in[5];
    const float* bq = (const float*)d_in[6];
    const float* Wv = (const float*)d_in[7];
    const float* bv = (const float*)d_in[8];
    const float* pri = (const float*)d_in[9];
    const float* msg = (const float*)d_in[10];
    const float* gamma = (const float*)d_in[11];
    const float* beta = (const float*)d_in[12];
    const int* esrc = (const int*)d_in[13];
    const int* edst = (const int*)d_in[14];
    float* out = (float*)d_out;

    init_all_kernel<<<1184, 256>>>();

    dim3 kqv_grid(690, 3);
    kqv_fused_kernel<<<kqv_grid, 256>>>(xw, xt, xd, Wk, bk, Wq, bq, Wv, bv);

    edge_fused_kernel<<<8 * BPE, 256>>>(esrc, edst, pri);

    final_fused_kernel<<<(NTOT * 32 + 255) / 256, 256>>>(msg, gamma, beta, out);
}

// round 5
// speedup vs baseline: 2.6272x; 1.1693x over previous
#include <cuda_runtime.h>
#include <cuda_fp16.h>

#define NWORD  20000
#define NTOPIC 50
#define NDOC   2000
#define NTOT   22050
#define INDIM  256
#define OUTDIM 128
#define NHEAD  8
#define NEDGE  150000
#define UROWS  64150

// ---------------- scratch ----------------
__device__ __align__(16) __half g_kh[NTOT * OUTDIM];
__device__ __align__(16) __half g_qh[NTOT * OUTDIM];
__device__ __align__(16) __half g_vh[NTOT * OUTDIM];
__device__ __align__(16) float g_u[(size_t)UROWS * OUTDIM];   // unnormalized sum(ex*v)
__device__ __align__(16) float g_den[UROWS * NHEAD];          // sum(ex)

// per-etype tables
__constant__ int c_sbase[8] = {0, 0, 20000, 20000, 0, 20000, 20050, 20050};
__constant__ int c_dbase[8] = {20000, 20050, 20050, 20000, 0, 0, 20000, 0};
__constant__ int c_uoff[8]  = {0, 50, 2050, 4050, 4100, 24100, 44100, 44150};
__constant__ int c_topic[8] = {1, 0, 0, 1, 0, 0, 1, 0};
__constant__ int c_elist[3][3] = {{4, 5, 7}, {0, 3, 6}, {1, 2, 0}};
__constant__ int c_nel[3] = {3, 3, 2};

#define BPE 148
#define NWRP (BPE * 8)

// warp partition for the final kernel (4 nodes per warp, ntype-uniform warps)
#define WWORD 5000
#define WTOPIC 13
#define WTOT 5513   // 5000 + 13 + 500

// ---------------- helpers ----------------
__device__ __forceinline__ void ffma2(unsigned long long& d, unsigned long long a,
                                      unsigned long long b) {
    asm("fma.rn.f32x2 %0, %1, %2, %0;" : "+l"(d) : "l"(a), "l"(b));
}
__device__ __forceinline__ unsigned long long pack2(float x) {
    unsigned long long r;
    asm("mov.b64 %0, {%1, %1};" : "=l"(r) : "f"(x));
    return r;
}
__device__ __forceinline__ float2 unpack2(unsigned long long v) {
    float2 f;
    asm("mov.b64 {%0, %1}, %2;" : "=f"(f.x), "=f"(f.y) : "l"(v));
    return f;
}
__device__ __forceinline__ void red_add_v4(float* p, float4 v) {
    asm volatile("red.global.add.v4.f32 [%0], {%1, %2, %3, %4};"
                 :: "l"(p), "f"(v.x), "f"(v.y), "f"(v.z), "f"(v.w) : "memory");
}
__device__ __forceinline__ void red_add_f32(float* p, float v) {
    asm volatile("red.global.add.f32 [%0], %1;" :: "l"(p), "f"(v) : "memory");
}

// ---------------- init: zero u and den ----------------
__global__ void init_all_kernel() {
    int tid = blockIdx.x * blockDim.x + threadIdx.x;
    int nth = gridDim.x * blockDim.x;
    float4 z4 = make_float4(0.f, 0.f, 0.f, 0.f);
    for (size_t i = tid; i < (size_t)UROWS * OUTDIM / 4; i += nth) ((float4*)g_u)[i] = z4;
    for (int i = tid; i < UROWS * NHEAD / 4; i += nth) ((float4*)g_den)[i] = z4;
}

// ---------------- kqv (FFMA2, half output): grid (690 node-tiles, 3 matrices) ----------------
__global__ void kqv_fused_kernel(const float* __restrict__ xw, const float* __restrict__ xt,
                                 const float* __restrict__ xd,
                                 const float* __restrict__ Wk, const float* __restrict__ bk,
                                 const float* __restrict__ Wq, const float* __restrict__ bq,
                                 const float* __restrict__ Wv, const float* __restrict__ bv) {
    __shared__ __align__(16) float xs[32 * INDIM];
    int bx = blockIdx.x;
    int t, n0, N, gbase;
    const float* x;
    if (bx < 625)      { t = 0; n0 = bx * 32;         N = NWORD;  gbase = 0;      x = xw; }
    else if (bx < 627) { t = 1; n0 = (bx - 625) * 32; N = NTOPIC; gbase = NWORD;  x = xt; }
    else               { t = 2; n0 = (bx - 627) * 32; N = NDOC;   gbase = NWORD + NTOPIC; x = xd; }

    int m = blockIdx.y;
    const float* W = (m == 0 ? Wk : (m == 1 ? Wq : Wv)) + (size_t)t * INDIM * OUTDIM;
    const float* bb = (m == 0 ? bk : (m == 1 ? bq : bv)) + t * OUTDIM;
    __half* outp = (m == 0 ? g_kh : (m == 1 ? g_qh : g_vh));

    int tid = threadIdx.x;
    for (int idx = tid; idx < 32 * INDIM; idx += 256) {
        int r = idx >> 8, c = idx & 255;
        int n = n0 + r;
        xs[idx] = (n < N) ? x[(size_t)n * INDIM + c] : 0.0f;
    }
    __syncthreads();

    int ty = tid >> 5, tx = tid & 31;
    int c0 = tx * 4;
    int r0 = ty * 4;

    unsigned long long acc2[4][2];
#pragma unroll
    for (int r = 0; r < 4; r++) { acc2[r][0] = 0ull; acc2[r][1] = 0ull; }

#pragma unroll 4
    for (int kk = 0; kk < INDIM; kk += 4) {
        float4 xv0 = *(const float4*)&xs[(r0 + 0) * INDIM + kk];
        float4 xv1 = *(const float4*)&xs[(r0 + 1) * INDIM + kk];
        float4 xv2 = *(const float4*)&xs[(r0 + 2) * INDIM + kk];
        float4 xv3 = *(const float4*)&xs[(r0 + 3) * INDIM + kk];
        ulonglong2 w0 = __ldg((const ulonglong2*)&W[(kk + 0) * OUTDIM + c0]);
        ulonglong2 w1 = __ldg((const ulonglong2*)&W[(kk + 1) * OUTDIM + c0]);
        ulonglong2 w2 = __ldg((const ulonglong2*)&W[(kk + 2) * OUTDIM + c0]);
        ulonglong2 w3 = __ldg((const ulonglong2*)&W[(kk + 3) * OUTDIM + c0]);
#pragma unroll
        for (int r = 0; r < 4; r++) {
            float4 xv = (r == 0) ? xv0 : (r == 1) ? xv1 : (r == 2) ? xv2 : xv3;
            unsigned long long p0 = pack2(xv.x);
            ffma2(acc2[r][0], p0, w0.x); ffma2(acc2[r][1], p0, w0.y);
            unsigned long long p1 = pack2(xv.y);
            ffma2(acc2[r][0], p1, w1.x); ffma2(acc2[r][1], p1, w1.y);
            unsigned long long p2 = pack2(xv.z);
            ffma2(acc2[r][0], p2, w2.x); ffma2(acc2[r][1], p2, w2.y);
            unsigned long long p3 = pack2(xv.w);
            ffma2(acc2[r][0], p3, w3.x); ffma2(acc2[r][1], p3, w3.y);
        }
    }

    float4 b4 = __ldg((const float4*)&bb[c0]);
#pragma unroll
    for (int r = 0; r < 4; r++) {
        int n = n0 + r0 + r;
        if (n < N) {
            float2 lo = unpack2(acc2[r][0]);
            float2 hi = unpack2(acc2[r][1]);
            union { uint2 u; __half2 h[2]; } pk;
            pk.h[0] = __floats2half2_rn(lo.x + b4.x, lo.y + b4.y);
            pk.h[1] = __floats2half2_rn(hi.x + b4.z, hi.y + b4.w);
            *(uint2*)&outp[(size_t)(gbase + n) * OUTDIM + c0] = pk.u;
        }
    }
}

// ---------------- fused edge pass (half gathers), unroll x4 ----------------
__global__ void __launch_bounds__(256, 3)
edge_fused_kernel(const int* __restrict__ esrc, const int* __restrict__ edst,
                  const float* __restrict__ pri) {
    __shared__ float us[NTOPIC * OUTDIM];   // 25.6 KB
    __shared__ float ds[NTOPIC * NHEAD];    // 1.6 KB
    int e = blockIdx.x / BPE;
    int blk = blockIdx.x - e * BPE;
    bool topic = c_topic[e];
    if (topic) {
        for (int i = threadIdx.x; i < NTOPIC * OUTDIM; i += 256) us[i] = 0.0f;
        for (int i = threadIdx.x; i < NTOPIC * NHEAD; i += 256) ds[i] = 0.0f;
        __syncthreads();
    }
    const int* src = esrc + (size_t)e * NEDGE;
    const int* dst = edst + (size_t)e * NEDGE;
    float* u = g_u + (size_t)c_uoff[e] * OUTDIM;
    float* den = g_den + (size_t)c_uoff[e] * NHEAD;
    int sbase = c_sbase[e], dbase = c_dbase[e];

    int lane = threadIdx.x & 31;
    int h = lane >> 2;
    int w = blk * 8 + (threadIdx.x >> 5);
    float prih = __ldg(&pri[e * NHEAD + h]) * 0.25f;

    for (int base = w; base < NEDGE; base += NWRP * 4) {
        int ss[4], dd[4];
        bool act[4];
        uint2 q2[4], k2[4], v2[4];
#pragma unroll
        for (int j = 0; j < 4; j++) {
            int i = base + j * NWRP;
            act[j] = (i < NEDGE);
            if (act[j]) { ss[j] = __ldg(src + i); dd[j] = __ldg(dst + i); }
        }
#pragma unroll
        for (int j = 0; j < 4; j++) {
            if (act[j]) {
                q2[j] = __ldg((const uint2*)(g_qh + (size_t)(dbase + dd[j]) * OUTDIM) + lane);
                k2[j] = __ldg((const uint2*)(g_kh + (size_t)(sbase + ss[j]) * OUTDIM) + lane);
                v2[j] = __ldg((const uint2*)(g_vh + (size_t)(sbase + ss[j]) * OUTDIM) + lane);
            }
        }
#pragma unroll
        for (int j = 0; j < 4; j++) {
            if (act[j]) {
                float2 qa = __half22float2(*(__half2*)&q2[j].x);
                float2 qb = __half22float2(*(__half2*)&q2[j].y);
                float2 ka = __half22float2(*(__half2*)&k2[j].x);
                float2 kb = __half22float2(*(__half2*)&k2[j].y);
                float p = qa.x * ka.x + qa.y * ka.y + qb.x * kb.x + qb.y * kb.y;
                p += __shfl_xor_sync(0xffffffffu, p, 1);
                p += __shfl_xor_sync(0xffffffffu, p, 2);
                float ex = __expf(p * prih);
                float2 va = __half22float2(*(__half2*)&v2[j].x);
                float2 vb = __half22float2(*(__half2*)&v2[j].y);
                float4 vv = make_float4(va.x * ex, va.y * ex, vb.x * ex, vb.y * ex);
                int d = dd[j];
                if (topic) {
                    float* pp = &us[d * OUTDIM + lane * 4];
                    atomicAdd(pp + 0, vv.x); atomicAdd(pp + 1, vv.y);
                    atomicAdd(pp + 2, vv.z); atomicAdd(pp + 3, vv.w);
                    if ((lane & 3) == 0) atomicAdd(&ds[d * NHEAD + h], ex);
                } else {
                    red_add_v4(&u[(size_t)d * OUTDIM + lane * 4], vv);
                    if ((lane & 3) == 0) red_add_f32(&den[d * NHEAD + h], ex);
                }
            }
        }
    }
    if (topic) {
        __syncthreads();
        for (int i = threadIdx.x; i < NTOPIC * OUTDIM; i += 256)
            if (us[i] != 0.0f) red_add_f32(&u[i], us[i]);
        for (int i = threadIdx.x; i < NTOPIC * NHEAD; i += 256)
            if (ds[i] != 0.0f) red_add_f32(&den[i], ds[i]);
    }
}

// ---------------- fused epilogue + final: 4 nodes/warp, msg hoisted ----------------
__global__ void final_fused_kernel(const float* __restrict__ msg,
                                   const float* __restrict__ gamma,
                                   const float* __restrict__ beta,
                                   float* __restrict__ out) {
    int gwarp = (blockIdx.x * blockDim.x + threadIdx.x) >> 5;
    if (gwarp >= WTOT) return;
    int lane = threadIdx.x & 31;
    int h = lane >> 2, j = lane & 3;

    int t, n0, Nt, gbase;
    if (gwarp < WWORD)               { t = 0; n0 = gwarp * 4;            Nt = NWORD;  gbase = 0; }
    else if (gwarp < WWORD + WTOPIC) { t = 1; n0 = (gwarp - WWORD) * 4;  Nt = NTOPIC; gbase = NWORD; }
    else                             { t = 2; n0 = (gwarp - WWORD - WTOPIC) * 4; Nt = NDOC; gbase = NWORD + NTOPIC; }
    int nel = c_nel[t];
    int nn_max = Nt - n0; if (nn_max > 4) nn_max = 4;

    unsigned long long acc2[4][2];
#pragma unroll
    for (int nn = 0; nn < 4; nn++) { acc2[nn][0] = 0ull; acc2[nn][1] = 0ull; }

#pragma unroll 3
    for (int ei = 0; ei < 3; ei++) {
        if (ei >= nel) break;
        int e = c_elist[t][ei];
        const float* msg_e = msg + (size_t)e * NHEAD * 256;
        ulonglong2 mv[16];
#pragma unroll
        for (int dd = 0; dd < 16; dd++)
            mv[dd] = __ldg((const ulonglong2*)&msg_e[(h * 16 + dd) * 16 + j * 4]);

        int uoff = c_uoff[e];
#pragma unroll
        for (int nn = 0; nn < 4; nn++) {
            if (nn >= nn_max) break;
            size_t row = (size_t)(uoff + n0 + nn);
            float dv = __ldg(&g_den[row * NHEAD + h]);
            float inv = (dv > 0.0f) ? __fdividef(1.0f, dv) : 0.0f;
            const float4* up = (const float4*)(g_u + row * OUTDIM + h * 16);
            float4 u0 = up[0], u1 = up[1], u2 = up[2], u3 = up[3];
            float uu[16] = {u0.x * inv, u0.y * inv, u0.z * inv, u0.w * inv,
                            u1.x * inv, u1.y * inv, u1.z * inv, u1.w * inv,
                            u2.x * inv, u2.y * inv, u2.z * inv, u2.w * inv,
                            u3.x * inv, u3.y * inv, u3.z * inv, u3.w * inv};
#pragma unroll
            for (int dd = 0; dd < 16; dd++) {
                unsigned long long sb = pack2(uu[dd]);
                ffma2(acc2[nn][0], sb, mv[dd].x);
                ffma2(acc2[nn][1], sb, mv[dd].y);
            }
        }
    }

    float invc = (t == 2) ? 0.5f : (1.0f / 3.0f);
    float4 g = __ldg((const float4*)&gamma[t * OUTDIM + lane * 4]);
    float4 b = __ldg((const float4*)&beta[t * OUTDIM + lane * 4]);

#pragma unroll
    for (int nn = 0; nn < 4; nn++) {
        if (nn >= nn_max) break;
        float2 a01 = unpack2(acc2[nn][0]);
        float2 a23 = unpack2(acc2[nn][1]);
        float4 hh;
        hh.x = fmaxf(a01.x * invc, 0.f); hh.y = fmaxf(a01.y * invc, 0.f);
        hh.z = fmaxf(a23.x * invc, 0.f); hh.w = fmaxf(a23.y * invc, 0.f);

        float s = hh.x + hh.y + hh.z + hh.w;
#pragma unroll
        for (int o = 16; o; o >>= 1) s += __shfl_xor_sync(0xffffffffu, s, o);
        float mu = s * (1.0f / 128.0f);

        float dx = hh.x - mu, dy = hh.y - mu, dz = hh.z - mu, dw = hh.w - mu;
        float ssq = dx * dx + dy * dy + dz * dz + dw * dw;
#pragma unroll
        for (int o = 16; o; o >>= 1) ssq += __shfl_xor_sync(0xffffffffu, ssq, o);
        float rstd = rsqrtf(ssq * (1.0f / 128.0f) + 1e-5f);

        float4 o4;
        o4.x = dx * rstd * g.x + b.x;
        o4.y = dy * rstd * g.y + b.y;
        o4.z = dz * rstd * g.z + b.z;
        o4.w = dw * rstd * g.w + b.w;
        *(float4*)&out[(size_t)(gbase + n0 + nn) * OUTDIM + lane * 4] = o4;
    }
}

// ---------------- host ----------------
extern "C" void kernel_launch(void* const* d_in, const int* in_sizes, int n_in,
                              void* d_out, int out_size) {
    const float* xw = (const float*)d_in[0];
    const float* xt = (const float*)d_in[1];
    const float* xd = (const float*)d_in[2];
    const float* Wk = (const float*)d_in[3];
    const float* bk = (const float*)d_in[4];
    const float* Wq = (const float*)d_in[5];
    const float* bq = (const float*)d_in[6];
    const float* Wv = (const float*)d_in[7];
    const float* bv = (const float*)d_in[8];
    const float* pri = (const float*)d_in[9];
    const float* msg = (const float*)d_in[10];
    const float* gamma = (const float*)d_in[11];
    const float* beta = (const float*)d_in[12];
    const int* esrc = (const int*)d_in[13];
    const int* edst = (const int*)d_in[14];
    float* out = (float*)d_out;

    init_all_kernel<<<1184, 256>>>();

    dim3 kqv_grid(690, 3);
    kqv_fused_kernel<<<kqv_grid, 256>>>(xw, xt, xd, Wk, bk, Wq, bq, Wv, bv);

    edge_fused_kernel<<<8 * BPE, 256>>>(esrc, edst, pri);

    final_fused_kernel<<<(WTOT * 32 + 127) / 128, 128>>>(msg, gamma, beta, out);
}